// round 14
// baseline (speedup 1.0000x reference)
#include <cuda_runtime.h>
#include <cstdint>

// ---------------------------------------------------------------------------
// DisentanglementModule loss, closed form (TAU_POS == TAU_NEG => tau cancels):
//   loss_x = S_pos/c_pos - S_neg/c_neg
//   S_pos  = sum_g (n_g * q_g - ||m_g||^2) / d
//   S_all  = (B * Q - ||M||^2) / d ,  S_neg = S_all - S_pos
// Column-separable: per-column per-group sums (m) + sums-of-squares (q).
//
// Flattened column space: 384 float4 "slots", warp-aligned per matrix:
//   slots [0,256)    rep  (1024 cols)
//   slots [256,272)  act0 (64 cols); [272,288) pad
//   slots [288,320)  act1 (128 cols)
//   slots [320,384)  act2 (256 cols)
//
// kA: grid (3,128). cp.async 4-stage ring, DEPTH-3 in flight (24KB/block);
//     threads consume only their own staged 16B -> no barriers in the loop.
// kBC: 48 blocks x 256 thr; batched (MLP-8) chunk reduction -> reduced plane;
//     LAST block (atomic ticket, fixed-order combines) finalizes the loss.
// ---------------------------------------------------------------------------

#define NB      4096
#define NCHUNK  128
#define RPC     32                  // rows per chunk (NCHUNK*RPC == NB)
#define NSTAGE  8                   // pipeline stages per chunk (4 rows each)
#define NSLOT   384
#define KB_BLK  48
#define FULL    0xFFFFFFFFu

// Scratch: every element rewritten each launch; g_ctr re-armed by last block
// -> graph-replay safe. No float atomics anywhere (deterministic).
__device__ __align__(16) float4 g_Spart[NCHUNK * 4 * NSLOT]; // 3.1MB
__device__ float  g_Qpart[NCHUNK * 4 * NSLOT];               // 786KB
__device__ __align__(16) float4 g_S2[4 * NSLOT];             // 24KB
__device__ float  g_Q2[4 * NSLOT];                           // 6KB
__device__ int    g_ctr = 0;

#define F4Z make_float4(0.f, 0.f, 0.f, 0.f)
__device__ __forceinline__ void f4add(float4& a, const float4 b) {
    a.x += b.x; a.y += b.y; a.z += b.z; a.w += b.w;
}

#define CPASYNC16(sa, ga) \
    asm volatile("cp.async.cg.shared.global [%0], [%1], 16;" :: "r"(sa), "l"(ga))
#define CPCOMMIT()  asm volatile("cp.async.commit_group;" ::: "memory")
#define CPWAIT2()   asm volatile("cp.async.wait_group 2;" ::: "memory")
#define CPWAIT1()   asm volatile("cp.async.wait_group 1;" ::: "memory")
#define CPWAIT0()   asm volatile("cp.async.wait_group 0;" ::: "memory")

// int64-vs-int32 detection: values in [0,3]; if int64 (LE), odd words are 0
// and even words <= 3. Vote over first 1024 pairs via __syncthreads_count.
__device__ __forceinline__ int detect_int64(const int* __restrict__ nl, int tid, int nthr) {
    int bad = 0;
    for (int i = tid; i < 1024; i += nthr) {
        const int lo = nl[2 * i], hi = nl[2 * i + 1];
        if (hi != 0 || (unsigned)lo > 3u) bad = 1;
    }
    return __syncthreads_count(bad) == 0;
}

// ---------------------------------------------------------------------------
// kA: cp.async deep-pipelined streaming. grid=(3, NCHUNK), 128 thr = slots.
// (UNCHANGED from R13 — measured ~4us.)
// ---------------------------------------------------------------------------
#define ACC8(S, T, x) do {                                   \
    S.x += x.x; S.y += x.y; S.z += x.z; S.w += x.w;          \
    T.x = fmaf(x.x, x.x, T.x); T.y = fmaf(x.y, x.y, T.y);    \
    T.z = fmaf(x.z, x.z, T.z); T.w = fmaf(x.w, x.w, T.w); } while (0)

__global__ __launch_bounds__(128) void kA_partial(
    const float* __restrict__ rep, const float* __restrict__ a0,
    const float* __restrict__ a1,  const float* __restrict__ a2,
    const int* __restrict__ nl)
{
    __shared__ float4 buf[4][4][128];            // 32KB, 4-stage ring x 4 rows
    const int tid   = threadIdx.x;
    const int slot  = blockIdx.x * 128 + tid;
    const int chunk = blockIdx.y;
    const int row0  = chunk * RPC;

    const int is64 = detect_int64(nl, tid, 128); // barrier inside
    __shared__ int gsh[RPC];
    if (tid < RPC)
        gsh[tid] = (is64 ? nl[2 * (row0 + tid)] : nl[row0 + tid]) & 3;
    __syncthreads();

    // Slot -> (src, ld, col). act2 owns [320,384) fully; pad = [272,288).
    const float* src; int ld, col, active = 1;
    if (slot < 256)      { src = rep; ld = 1024; col = slot * 4; }
    else if (slot < 272) { src = a0;  ld = 512;  col = (slot - 256) * 4; }
    else if (slot < 288) { src = a0;  ld = 512;  col = 0; active = 0; }  // pad
    else if (slot < 320) { src = a1;  ld = 512;  col = (slot - 288) * 4; }
    else                 { src = a2;  ld = 512;  col = (slot - 320) * 4; }

    const float* p = src + (size_t)row0 * ld + col;
    const uint32_t sbase = (uint32_t)__cvta_generic_to_shared(&buf[0][0][tid]);

    float4 sA = F4Z, sB = F4Z, sC = F4Z, sD = F4Z;
    float4 tA = F4Z, tB = F4Z, tC = F4Z, tD = F4Z;

    // Prologue: commit stages 0..2 -> 3 groups (24KB/block) in flight.
    #pragma unroll
    for (int s = 0; s < 3; s++) {
        if (active) {
            #pragma unroll
            for (int r = 0; r < 4; r++)
                CPASYNC16(sbase + (s * 4 + r) * 2048, p + (size_t)(s * 4 + r) * ld);
        }
        CPCOMMIT();
    }

    #pragma unroll
    for (int i = 0; i < NSTAGE; i++) {
        if (i < 6)       CPWAIT2();
        else if (i == 6) CPWAIT1();
        else             CPWAIT0();

        if (i + 3 < NSTAGE) {
            if (active) {
                const int b1 = (i + 3) & 3;
                #pragma unroll
                for (int r = 0; r < 4; r++)
                    CPASYNC16(sbase + (b1 * 4 + r) * 2048,
                              p + (size_t)((i + 3) * 4 + r) * ld);
            }
            CPCOMMIT();
        }

        if (active) {
            const int b = i & 3;
            #pragma unroll
            for (int r = 0; r < 4; r++) {
                const float4 x = buf[b][r][tid];
                const int g = gsh[i * 4 + r];               // warp-uniform
                if      (g == 0) ACC8(sA, tA, x);
                else if (g == 1) ACC8(sB, tB, x);
                else if (g == 2) ACC8(sC, tC, x);
                else             ACC8(sD, tD, x);
            }
        }
    }

    const int base = (chunk * 4) * NSLOT + slot;
    g_Spart[base + 0 * NSLOT] = sA;
    g_Spart[base + 1 * NSLOT] = sB;
    g_Spart[base + 2 * NSLOT] = sC;
    g_Spart[base + 3 * NSLOT] = sD;
    g_Qpart[base + 0 * NSLOT] = tA.x + tA.y + tA.z + tA.w;
    g_Qpart[base + 1 * NSLOT] = tB.x + tB.y + tB.z + tB.w;
    g_Qpart[base + 2 * NSLOT] = tC.x + tC.y + tC.z + tC.w;
    g_Qpart[base + 3 * NSLOT] = tD.x + tD.y + tD.z + tD.w;
}

// ---------------------------------------------------------------------------
// kBC: reduce + finalize. grid = 48 x 256.
// Thread = (sl=tid&7, g=(tid>>3)&3, part=tid>>5); part sums 16 chunks with
// EXPLICIT 8-deep load batching (MLP). Shared combine over parts -> plane.
// Last block (ticket) finalizes: pass0 warps 0-7 = slots 0-255 (rep/m0),
// pass1 warps 0-3 = slots 256-383 (m1/m2/m3) -> same wr[12][9] as before.
// ---------------------------------------------------------------------------
__global__ __launch_bounds__(256) void kBC_reduce_final(
    const int* __restrict__ nl, float* __restrict__ out, int out_size)
{
    const int tid  = threadIdx.x;
    const int sl   = tid & 7;
    const int g    = (tid >> 3) & 3;
    const int part = tid >> 5;           // 0..7 (== warp id)
    const int slot = blockIdx.x * 8 + sl;
    const int lane = tid & 31, warp = tid >> 5;

    float4 S = F4Z; float Q = 0.f;
    const int c0 = part * 16;
    #pragma unroll
    for (int cc = 0; cc < 16; cc += 8) {
        float4 v[8]; float w[8];
        #pragma unroll
        for (int u = 0; u < 8; u++) {                 // batch: 16 indep loads
            const int b = ((c0 + cc + u) * 4 + g) * NSLOT + slot;
            v[u] = g_Spart[b];
            w[u] = g_Qpart[b];
        }
        #pragma unroll
        for (int u = 0; u < 8; u++) { f4add(S, v[u]); Q += w[u]; }
    }

    __shared__ float4 shS[256];
    __shared__ float  shQ[256];
    shS[tid] = S; shQ[tid] = Q;
    __syncthreads();

    if (tid < 32) {   // (g=tid>>3, sl=tid&7); combine parts, fixed order
        float4 Sf = F4Z; float Qf = 0.f;
        #pragma unroll
        for (int p = 0; p < 8; p++) {
            f4add(Sf, shS[p * 32 + tid]);
            Qf += shQ[p * 32 + tid];
        }
        const int og = tid >> 3, osl = blockIdx.x * 8 + (tid & 7);
        g_S2[og * NSLOT + osl] = Sf;
        g_Q2[og * NSLOT + osl] = Qf;
    }

    // ---- last-block ticket (arrive-and-exit; no spin, no deadlock) ----
    __threadfence();
    __shared__ int ticket;
    __syncthreads();                  // plane writes done before tid0 arrives
    if (tid == 0) ticket = atomicAdd(&g_ctr, 1);
    __syncthreads();
    if (ticket != KB_BLK - 1) return;
    __threadfence();                  // other blocks' g_S2/g_Q2 now visible

    // ---- finalize ----
    __shared__ double wr[12][9];
    {   // pass 0: slots 0..255 -> wr rows 0..7
        const int fslot = tid;
        float4 Sv[4]; float fq[4];
        #pragma unroll
        for (int gg = 0; gg < 4; gg++) {
            Sv[gg] = g_S2[gg * NSLOT + fslot];
            fq[gg] = g_Q2[gg * NSLOT + fslot];
        }
        double v[9];
        float4 st = F4Z;
        #pragma unroll
        for (int gg = 0; gg < 4; gg++) {
            v[gg] = (double)Sv[gg].x * Sv[gg].x + (double)Sv[gg].y * Sv[gg].y
                  + (double)Sv[gg].z * Sv[gg].z + (double)Sv[gg].w * Sv[gg].w;
            v[4 + gg] = (double)fq[gg];
            f4add(st, Sv[gg]);
        }
        v[8] = (double)st.x * st.x + (double)st.y * st.y
             + (double)st.z * st.z + (double)st.w * st.w;
        #pragma unroll
        for (int k = 0; k < 9; k++) {
            double x = v[k];
            #pragma unroll
            for (int off = 16; off > 0; off >>= 1)
                x += __shfl_down_sync(FULL, x, off);
            if (lane == 0) wr[warp][k] = x;
        }
    }
    if (tid < 128) {   // pass 1: slots 256..383 -> wr rows 8..11 (full warps)
        const int fslot = 256 + tid;
        float4 Sv[4]; float fq[4];
        #pragma unroll
        for (int gg = 0; gg < 4; gg++) {
            Sv[gg] = g_S2[gg * NSLOT + fslot];
            fq[gg] = g_Q2[gg * NSLOT + fslot];
        }
        double v[9];
        float4 st = F4Z;
        #pragma unroll
        for (int gg = 0; gg < 4; gg++) {
            v[gg] = (double)Sv[gg].x * Sv[gg].x + (double)Sv[gg].y * Sv[gg].y
                  + (double)Sv[gg].z * Sv[gg].z + (double)Sv[gg].w * Sv[gg].w;
            v[4 + gg] = (double)fq[gg];
            f4add(st, Sv[gg]);
        }
        v[8] = (double)st.x * st.x + (double)st.y * st.y
             + (double)st.z * st.z + (double)st.w * st.w;
        #pragma unroll
        for (int k = 0; k < 9; k++) {
            double x = v[k];
            #pragma unroll
            for (int off = 16; off > 0; off >>= 1)
                x += __shfl_down_sync(FULL, x, off);
            if (lane == 0) wr[8 + warp][k] = x;
        }
    }

    // Group counts (detect has a barrier inside, also orders wr writes).
    const int is64 = detect_int64(nl, tid, 256);
    int c[4] = {0, 0, 0, 0};
    for (int i = tid; i < NB; i += 256) {
        const int gg = (is64 ? nl[2 * i] : nl[i]) & 3;
        c[gg]++;
    }
    __shared__ int cw[4][8];
    __shared__ int cnt_sh[4];
    #pragma unroll
    for (int gg = 0; gg < 4; gg++) {
        int x = c[gg];
        #pragma unroll
        for (int off = 16; off > 0; off >>= 1) x += __shfl_down_sync(FULL, x, off);
        if (lane == 0) cw[gg][warp] = x;
    }
    __syncthreads();
    if (tid < 4) {
        int t = 0;
        #pragma unroll
        for (int w = 0; w < 8; w++) t += cw[tid][w];
        cnt_sh[tid] = t;
    }
    __syncthreads();

    if (tid == 0) {
        double msq[16], qm[16], Msq[4];
        #pragma unroll
        for (int k = 0; k < 16; k++) { msq[k] = 0.0; qm[k] = 0.0; }
        #pragma unroll
        for (int m = 0; m < 4; m++) Msq[m] = 0.0;
        #pragma unroll
        for (int w = 0; w < 12; w++) {
            const int m = (w < 8) ? 0 : (w == 8) ? 1 : (w == 9) ? 2 : 3;
            #pragma unroll
            for (int gg = 0; gg < 4; gg++) {
                msq[m * 4 + gg] += wr[w][gg];
                qm [m * 4 + gg] += wr[w][4 + gg];
            }
            Msq[m] += wr[w][8];
        }

        double n[4], cpos = 0.0;
        #pragma unroll
        for (int gg = 0; gg < 4; gg++) {
            n[gg] = (double)cnt_sh[gg];
            cpos += 0.5 * n[gg] * (n[gg] - 1.0);
        }
        const double Bv = (double)NB;
        const double cneg = 0.5 * Bv * (Bv - 1.0) - cpos;
        const double icp = 1.0 / cpos, icn = 1.0 / cneg;
        const double idm[4] = {1.0/1024.0, 1.0/64.0, 1.0/128.0, 1.0/256.0};

        double loss[4];
        #pragma unroll
        for (int m = 0; m < 4; m++) {
            double Spos = 0.0, Qm = 0.0;
            #pragma unroll
            for (int gg = 0; gg < 4; gg++) {
                Spos += n[gg] * qm[m * 4 + gg] - msq[m * 4 + gg];
                Qm   += qm[m * 4 + gg];
            }
            Spos *= idm[m];
            const double Sall = (Bv * Qm - Msq[m]) * idm[m];
            const double Sneg = Sall - Spos;
            loss[m] = Spos * icp - Sneg * icn;
        }
        const double latent = (loss[1] + loss[2] + loss[3]) * (1.0 / 3.0);
        out[0] = (float)(0.5 * latent + 0.5 * loss[0]);      // W = 0.5
        g_ctr = 0;                                           // re-arm for replay
    }
    for (int i = 1 + tid; i < out_size; i += 256) out[i] = 0.0f;
}

// ---------------------------------------------------------------------------
extern "C" void kernel_launch(void* const* d_in, const int* in_sizes, int n_in,
                              void* d_out, int out_size) {
    const float* rep = (const float*)d_in[0];
    const float* a0  = (const float*)d_in[1];
    const float* a1  = (const float*)d_in[2];
    const float* a2  = (const float*)d_in[3];
    const int*   nl  = (const int*)d_in[4];

    kA_partial<<<dim3(3, NCHUNK), 128>>>(rep, a0, a1, a2, nl);
    kBC_reduce_final<<<KB_BLK, 256>>>(nl, (float*)d_out, out_size);
}